// round 13
// baseline (speedup 1.0000x reference)
#include <cuda_runtime.h>
#include <cuda_bf16.h>
#include <cuda_fp16.h>
#include <cstdint>

#define Nv   200000
#define Kk   27
#define Mm   100000
#define Bb   4
#define EPSf 1e-5f
#define C2_TPK 782                 // tiles per k offset (ceil(Mm/128))
#define C2_TILES (Kk * C2_TPK)     // 21114
#define C2_GRID 296                // 2 CTAs/SM * 148

// ---------------- scratch (device globals — no runtime allocation) ----------
__device__ __half g_x1r[(size_t)Nv * 64];        // conv1 out (raw, fp16)
__device__ float  g_x2[(size_t)Nv * 64];         // conv2 accum (raw, fp32)
__device__ __half g_x1h[(size_t)Nv * 64];        // normalized x1, fp16
__device__ __half g_x2h[(size_t)Nv * 64];        // normalized x2, fp16
__device__ __half g_x3h[(size_t)Nv * 256];       // conv3 out (raw, fp16)
__device__ __half g_W1h[64 * 256];               // [d][c] col-major fp16
__device__ __half g_W2h[Kk * 4096];              // [k][d][c] fp16
__device__ __half g_W3h[256 * 64];               // [n][c] fp16
__device__ float g_sum1[Bb * 64], g_sq1[Bb * 64];
__device__ float g_sum2[Bb * 64], g_sq2[Bb * 64];
__device__ float g_sum3[Bb * 256], g_sq3[Bb * 256];
__device__ int   g_cnt[Bb];

// ---------------- helpers -----------------------------------------------------
__device__ __forceinline__ void red_v2(float* p, float a, float b) {
    asm volatile("red.global.add.v2.f32 [%0], {%1,%2};"
                 :: "l"(p), "f"(a), "f"(b) : "memory");
}
__device__ __forceinline__ uint32_t smem_u32(const void* p) {
    uint32_t a;
    asm("{ .reg .u64 t; cvta.to.shared.u64 t, %1; cvt.u32.u64 %0, t; }"
        : "=r"(a) : "l"(p));
    return a;
}
__device__ __forceinline__ void ldsm_x4(uint32_t* r, uint32_t addr) {
    asm volatile("ldmatrix.sync.aligned.m8n8.x4.shared.b16 {%0,%1,%2,%3}, [%4];"
        : "=r"(r[0]), "=r"(r[1]), "=r"(r[2]), "=r"(r[3]) : "r"(addr));
}
__device__ __forceinline__ void mma_f16(float* c, const uint32_t* a,
                                        uint32_t b0, uint32_t b1) {
    asm volatile("mma.sync.aligned.m16n8k16.row.col.f32.f16.f16.f32 "
        "{%0,%1,%2,%3}, {%4,%5,%6,%7}, {%8,%9}, {%0,%1,%2,%3};"
        : "+f"(c[0]), "+f"(c[1]), "+f"(c[2]), "+f"(c[3])
        : "r"(a[0]), "r"(a[1]), "r"(a[2]), "r"(a[3]), "r"(b0), "r"(b1));
}
__device__ __forceinline__ void cp16(uint32_t dst, const void* src, int sz) {
    asm volatile("cp.async.cg.shared.global [%0], [%1], 16, %2;"
                 :: "r"(dst), "l"(src), "r"(sz));
}
#define CP_COMMIT() asm volatile("cp.async.commit_group;" ::: "memory")
#define CP_WAIT0()  asm volatile("cp.async.wait_group 0;" ::: "memory")

__device__ __forceinline__ uint2 pack8h(float a0, float a1, float a2, float a3,
                                        float a4, float a5, float a6, float a7,
                                        uint2& hi) {
    __half2 h0 = __floats2half2_rn(a0, a1);
    __half2 h1 = __floats2half2_rn(a2, a3);
    __half2 h2 = __floats2half2_rn(a4, a5);
    __half2 h3 = __floats2half2_rn(a6, a7);
    uint2 lo;
    lo.x = *(uint32_t*)&h0; lo.y = *(uint32_t*)&h1;
    hi.x = *(uint32_t*)&h2; hi.y = *(uint32_t*)&h3;
    return lo;
}

// ---------------- small zero: stats accumulators + counts --------------------
__global__ void small_zero_kernel() {
    int t = threadIdx.x;
    for (int i = t; i < Bb * 64; i += 256) {
        g_sum1[i] = 0.f; g_sq1[i] = 0.f; g_sum2[i] = 0.f; g_sq2[i] = 0.f;
    }
    for (int i = t; i < Bb * 256; i += 256) { g_sum3[i] = 0.f; g_sq3[i] = 0.f; }
    if (t < Bb) g_cnt[t] = 0;
}

// ---------------- setup: zero g_x2 + weight fp16 + batch counts --------------
__global__ void __launch_bounds__(256) setup_kernel(const float* __restrict__ W1,
                                                    const float* __restrict__ W2,
                                                    const float* __restrict__ W3,
                                                    const int* __restrict__ batch_idx) {
    __shared__ int s_cnt[Bb];
    int t = threadIdx.x;
    if (t < Bb) s_cnt[t] = 0;
    __syncthreads();

    long long gi = (long long)blockIdx.x * blockDim.x + t;
    long long stride = (long long)gridDim.x * blockDim.x;

    {
        const long long total4 = (long long)Nv * 16;
        float4* p = reinterpret_cast<float4*>(g_x2);
        float4 z = make_float4(0.f, 0.f, 0.f, 0.f);
        for (long long j = gi; j < total4; j += stride) p[j] = z;
    }
    {
        long long i = gi;
        if (i < 16384) {
            int d = (int)(i >> 8), c = (int)(i & 255);
            g_W1h[i] = __float2half_rn(W1[c * 64 + d]);
        } else if (i < 16384 + Kk * 4096) {
            int j = (int)(i - 16384);
            int kk = j >> 12, r = j & 4095;
            int d = r >> 6, c = r & 63;
            g_W2h[j] = __float2half_rn(W2[kk * 4096 + c * 64 + d]);
        } else if (i < 16384 + Kk * 4096 + 16384) {
            int j = (int)(i - 16384 - Kk * 4096);
            int n = j >> 6, c = j & 63;
            g_W3h[j] = __float2half_rn(W3[c * 256 + n]);
        }
    }
    for (long long j = gi; j < Nv; j += stride) atomicAdd(&s_cnt[batch_idx[j]], 1);
    __syncthreads();
    if (t < Bb && s_cnt[t] != 0) atomicAdd(&g_cnt[t], s_cnt[t]);
}

// ---------------- conv1: mma.sync fp16, fused stats1, fp16 raw out -----------
__global__ void __launch_bounds__(256, 2) conv1_mma_kernel(const float* __restrict__ feats,
                                                           const int* __restrict__ batch_idx,
                                                           float* __restrict__ gsum,
                                                           float* __restrict__ gsq) {
    extern __shared__ __align__(16) char sm1[];
    __half* Ah = (__half*)sm1;
    __half* Wh = (__half*)(sm1 + 18432);
    float* Cs = (float*)sm1;
    __shared__ int s_b[128];
    __shared__ float sred[256], qred[256];

    int t = threadIdx.x;
    int row0 = blockIdx.x * 128;
    if (t < 128) {
        int r = row0 + t;
        s_b[t] = (r < Nv) ? batch_idx[r] : -1;
    }

    int wid = t >> 5, lane = t & 31;
    int mb = (wid >> 1) * 32;
    int nb = (wid & 1) * 32;
    int a_row = lane & 15;
    int a_koff = (lane >> 4) << 3;
    int b_n = (lane & 7) + ((lane >> 4) << 3);
    int b_koff = ((lane >> 3) & 1) << 3;

    float acc[2][4][4];
#pragma unroll
    for (int i = 0; i < 2; i++)
#pragma unroll
        for (int j = 0; j < 4; j++)
#pragma unroll
            for (int q = 0; q < 4; q++) acc[i][j][q] = 0.f;

    for (int k0 = 0; k0 < 256; k0 += 64) {
        __syncthreads();
#pragma unroll
        for (int e4 = t; e4 < 2048; e4 += 256) {
            int r = e4 >> 4, cg = e4 & 15;
            int row = row0 + r;
            float4 v = make_float4(0.f, 0.f, 0.f, 0.f);
            if (row < Nv) v = *(const float4*)&feats[(size_t)row * 256 + k0 + cg * 4];
            __half2 h0 = __floats2half2_rn(v.x, v.y);
            __half2 h1 = __floats2half2_rn(v.z, v.w);
            uint2 u;
            u.x = *(uint32_t*)&h0;
            u.y = *(uint32_t*)&h1;
            *(uint2*)&Ah[r * 72 + cg * 4] = u;
        }
#pragma unroll
        for (int e4 = t; e4 < 512; e4 += 256) {
            int d = e4 >> 3, q = e4 & 7;
            *(uint4*)&Wh[d * 72 + q * 8] = *(const uint4*)&g_W1h[d * 256 + k0 + q * 8];
        }
        __syncthreads();

#pragma unroll
        for (int ks = 0; ks < 4; ks++) {
            int kc = ks * 16;
            uint32_t af0[4], af1[4], bf0[4], bf1[4];
            ldsm_x4(af0, smem_u32(&Ah[(mb + a_row) * 72 + kc + a_koff]));
            ldsm_x4(af1, smem_u32(&Ah[(mb + 16 + a_row) * 72 + kc + a_koff]));
            ldsm_x4(bf0, smem_u32(&Wh[(nb + b_n) * 72 + kc + b_koff]));
            ldsm_x4(bf1, smem_u32(&Wh[(nb + 16 + b_n) * 72 + kc + b_koff]));
            mma_f16(acc[0][0], af0, bf0[0], bf0[1]);
            mma_f16(acc[0][1], af0, bf0[2], bf0[3]);
            mma_f16(acc[0][2], af0, bf1[0], bf1[1]);
            mma_f16(acc[0][3], af0, bf1[2], bf1[3]);
            mma_f16(acc[1][0], af1, bf0[0], bf0[1]);
            mma_f16(acc[1][1], af1, bf0[2], bf0[3]);
            mma_f16(acc[1][2], af1, bf1[0], bf1[1]);
            mma_f16(acc[1][3], af1, bf1[2], bf1[3]);
        }
    }

    __syncthreads();
    int g = lane >> 2, tg = lane & 3;
#pragma unroll
    for (int mi = 0; mi < 2; mi++) {
        int row = mb + mi * 16 + g;
#pragma unroll
        for (int nj = 0; nj < 4; nj++) {
            int col = nb + nj * 8 + tg * 2;
            *(float2*)&Cs[row * 68 + col]       = make_float2(acc[mi][nj][0], acc[mi][nj][1]);
            *(float2*)&Cs[(row + 8) * 68 + col] = make_float2(acc[mi][nj][2], acc[mi][nj][3]);
        }
    }
    __syncthreads();

    // write raw x1 as fp16 (8 ch per iteration)
#pragma unroll
    for (int e = t; e < 1024; e += 256) {
        int r = e >> 3, cg8 = e & 7;
        int row = row0 + r;
        if (row < Nv) {
            float4 v0 = *(const float4*)&Cs[r * 68 + cg8 * 8];
            float4 v1 = *(const float4*)&Cs[r * 68 + cg8 * 8 + 4];
            uint2 hi;
            uint2 lo = pack8h(v0.x, v0.y, v0.z, v0.w, v1.x, v1.y, v1.z, v1.w, hi);
            uint4 u = make_uint4(lo.x, lo.y, hi.x, hi.y);
            *(uint4*)&g_x1r[(size_t)row * 64 + cg8 * 8] = u;
        }
    }

    int b0 = s_b[0];
    bool fast;
    if (s_b[127] == b0) fast = true;
    else if (row0 + 127 >= Nv) {
        int lastr = Nv - 1 - row0;
        fast = (lastr >= 0 && s_b[lastr] == b0);
    } else fast = false;

    if (fast) {
        int col = t & 63, rg = t >> 6;
        float s = 0.f, q = 0.f;
#pragma unroll 8
        for (int r = rg * 32; r < rg * 32 + 32; r++) {
            float v = Cs[r * 68 + col];
            s += v; q += v * v;
        }
        sred[rg * 64 + col] = s;
        qred[rg * 64 + col] = q;
        __syncthreads();
        if (t < 64) {
            float v = sred[t] + sred[64 + t] + sred[128 + t] + sred[192 + t];
            atomicAdd(&gsum[b0 * 64 + t], v);
        } else if (t < 128) {
            int c = t - 64;
            float v = qred[c] + qred[64 + c] + qred[128 + c] + qred[192 + c];
            atomicAdd(&gsq[b0 * 64 + c], v);
        }
    } else {
        for (int e = t; e < 8192; e += 256) {
            int r = e >> 6, c = e & 63;
            if (row0 + r < Nv) {
                float v = Cs[r * 68 + c];
                int b = s_b[r];
                atomicAdd(&gsum[b * 64 + c], v);
                atomicAdd(&gsq[b * 64 + c], v * v);
            }
        }
    }
}

// ---------------- norm1: fp16 raw in -> fp16 normalized out ------------------
__global__ void __launch_bounds__(256) norm_h_kernel(const __half* __restrict__ x,
                                                     __half* __restrict__ oh,
                                                     const int* __restrict__ batch_idx,
                                                     const float* __restrict__ sumArr,
                                                     const float* __restrict__ sqArr) {
    __shared__ float s_m[Bb * 64], s_i[Bb * 64];
    int t = threadIdx.x;
    for (int i = t; i < Bb * 64; i += 256) {
        float cnt = (float)g_cnt[i >> 6];
        float mean = sumArr[i] / cnt;
        float var = sqArr[i] / cnt - mean * mean;
        s_m[i] = mean;
        s_i[i] = rsqrtf(fmaxf(var, 0.f) + EPSf);
    }
    __syncthreads();

    long long total = (long long)Nv * 8;   // 8-ch groups
    long long i = (long long)blockIdx.x * blockDim.x + t;
    long long stride = (long long)gridDim.x * blockDim.x;
    for (; i < total; i += stride) {
        int row = (int)(i >> 3);
        int cg8 = (int)(i & 7);
        int b = batch_idx[row];
        uint4 u = *(const uint4*)&x[(size_t)row * 64 + cg8 * 8];
        float4 m0 = ((const float4*)s_m)[b * 16 + cg8 * 2];
        float4 m1 = ((const float4*)s_m)[b * 16 + cg8 * 2 + 1];
        float4 s0 = ((const float4*)s_i)[b * 16 + cg8 * 2];
        float4 s1 = ((const float4*)s_i)[b * 16 + cg8 * 2 + 1];
        float2 f0 = __half22float2(*(__half2*)&u.x);
        float2 f1 = __half22float2(*(__half2*)&u.y);
        float2 f2 = __half22float2(*(__half2*)&u.z);
        float2 f3 = __half22float2(*(__half2*)&u.w);
        uint2 hi;
        uint2 lo = pack8h(fmaxf((f0.x - m0.x) * s0.x, 0.f),
                          fmaxf((f0.y - m0.y) * s0.y, 0.f),
                          fmaxf((f1.x - m0.z) * s0.z, 0.f),
                          fmaxf((f1.y - m0.w) * s0.w, 0.f),
                          fmaxf((f2.x - m1.x) * s1.x, 0.f),
                          fmaxf((f2.y - m1.y) * s1.y, 0.f),
                          fmaxf((f3.x - m1.z) * s1.z, 0.f),
                          fmaxf((f3.y - m1.w) * s1.w, 0.f), hi);
        *(uint4*)&oh[(size_t)row * 64 + cg8 * 8] = make_uint4(lo.x, lo.y, hi.x, hi.y);
    }
}

// ---------------- norm2: fp32 in -> fp16 normalized out ----------------------
__global__ void __launch_bounds__(256) norm_f_kernel(const float* __restrict__ x,
                                                     __half* __restrict__ oh,
                                                     const int* __restrict__ batch_idx,
                                                     const float* __restrict__ sumArr,
                                                     const float* __restrict__ sqArr) {
    __shared__ float s_m[Bb * 64], s_i[Bb * 64];
    int t = threadIdx.x;
    for (int i = t; i < Bb * 64; i += 256) {
        float cnt = (float)g_cnt[i >> 6];
        float mean = sumArr[i] / cnt;
        float var = sqArr[i] / cnt - mean * mean;
        s_m[i] = mean;
        s_i[i] = rsqrtf(fmaxf(var, 0.f) + EPSf);
    }
    __syncthreads();

    long long total = (long long)Nv * 8;
    long long i = (long long)blockIdx.x * blockDim.x + t;
    long long stride = (long long)gridDim.x * blockDim.x;
    for (; i < total; i += stride) {
        int row = (int)(i >> 3);
        int cg8 = (int)(i & 7);
        int b = batch_idx[row];
        float4 v0 = *(const float4*)&x[(size_t)row * 64 + cg8 * 8];
        float4 v1 = *(const float4*)&x[(size_t)row * 64 + cg8 * 8 + 4];
        float4 m0 = ((const float4*)s_m)[b * 16 + cg8 * 2];
        float4 m1 = ((const float4*)s_m)[b * 16 + cg8 * 2 + 1];
        float4 s0 = ((const float4*)s_i)[b * 16 + cg8 * 2];
        float4 s1 = ((const float4*)s_i)[b * 16 + cg8 * 2 + 1];
        uint2 hi;
        uint2 lo = pack8h(fmaxf((v0.x - m0.x) * s0.x, 0.f),
                          fmaxf((v0.y - m0.y) * s0.y, 0.f),
                          fmaxf((v0.z - m0.z) * s0.z, 0.f),
                          fmaxf((v0.w - m0.w) * s0.w, 0.f),
                          fmaxf((v1.x - m1.x) * s1.x, 0.f),
                          fmaxf((v1.y - m1.y) * s1.y, 0.f),
                          fmaxf((v1.z - m1.z) * s1.z, 0.f),
                          fmaxf((v1.w - m1.w) * s1.w, 0.f), hi);
        *(uint4*)&oh[(size_t)row * 64 + cg8 * 8] = make_uint4(lo.x, lo.y, hi.x, hi.y);
    }
}

// ---------------- conv2: persistent pipelined fp16 single-A gather-GEMM-scatter
__global__ void __launch_bounds__(256, 2) conv2_mma_kernel(const int* __restrict__ in_idx,
                                                           const int* __restrict__ out_idx) {
    extern __shared__ __align__(16) char sm2[];
    __half* Wh = (__half*)(sm2 + 36864);
    __shared__ int s_in[2][128], s_out[2][128];

    int t = threadIdx.x;
    int per = (C2_TILES + C2_GRID - 1) / C2_GRID;   // 72
    int start = blockIdx.x * per;
    int end = min(start + per, C2_TILES);
    if (start >= end) return;

    int wid = t >> 5, lane = t & 31;
    int mb = (wid >> 1) * 32;
    int nb = (wid & 1) * 32;
    int a_row = lane & 15;
    int a_koff = (lane >> 4) << 3;
    int b_n = (lane & 7) + ((lane >> 4) << 3);
    int b_koff = ((lane >> 3) & 1) << 3;
    int g = lane >> 2, tg = lane & 3;

    int cur_k = -1;

    {
        int k0 = start / C2_TPK;
        int m0 = (start % C2_TPK) * 128;
        if (t < 128) {
            int p = m0 + t;
            bool v = (p < Mm);
            s_in[0][t]  = v ? in_idx[(size_t)k0 * Mm + p] : -1;
            s_out[0][t] = v ? out_idx[(size_t)k0 * Mm + p] : -1;
        }
    }
    __syncthreads();
    {
        char* base = sm2;
#pragma unroll
        for (int e = t; e < 1024; e += 256) {
            int r = e >> 3, q = e & 7;
            int src = s_in[0][r];
            bool v = (src >= 0);
            size_t off = (size_t)(v ? src : 0) * 64 + q * 8;
            cp16(smem_u32(base + r * 144 + q * 16), g_x1h + off, v ? 16 : 0);
        }
        CP_COMMIT();
    }

    for (int i = start; i < end; i++) {
        int s = (i - start) & 1;
        int ns = s ^ 1;
        int k = i / C2_TPK;

        int ri = -1, ro = -1;
        bool have_next = (i + 1 < end);
        if (have_next && t < 128) {
            int nk = (i + 1) / C2_TPK;
            int m0 = ((i + 1) % C2_TPK) * 128;
            int p = m0 + t;
            if (p < Mm) {
                ri = in_idx[(size_t)nk * Mm + p];
                ro = out_idx[(size_t)nk * Mm + p];
            }
        }

        CP_WAIT0();
        __syncthreads();

        if (have_next && t < 128) { s_in[ns][t] = ri; s_out[ns][t] = ro; }
        if (k != cur_k) {
            const __half* Wkh = g_W2h + (size_t)k * 4096;
#pragma unroll
            for (int e4 = t; e4 < 512; e4 += 256) {
                int d = e4 >> 3, q = e4 & 7;
                *(uint4*)&Wh[d * 72 + q * 8] = *(const uint4*)&Wkh[d * 64 + q * 8];
            }
            cur_k = k;
        }
        __syncthreads();

        if (have_next) {
            char* base = sm2 + ns * 18432;
#pragma unroll
            for (int e = t; e < 1024; e += 256) {
                int r = e >> 3, q = e & 7;
                int src = s_in[ns][r];
                bool v = (src >= 0);
                size_t off = (size_t)(v ? src : 0) * 64 + q * 8;
                cp16(smem_u32(base + r * 144 + q * 16), g_x1h + off, v ? 16 : 0);
            }
            CP_COMMIT();
        }

        const __half* A = (const __half*)(sm2 + s * 18432);

        float acc[2][4][4];
#pragma unroll
        for (int ii = 0; ii < 2; ii++)
#pragma unroll
            for (int j = 0; j < 4; j++)
#pragma unroll
                for (int q = 0; q < 4; q++) acc[ii][j][q] = 0.f;

#pragma unroll
        for (int ks = 0; ks < 4; ks++) {
            int k0 = ks * 16;
            uint32_t af0[4], af1[4], bf0[4], bf1[4];
            ldsm_x4(af0, smem_u32(&A[(mb + a_row) * 72 + k0 + a_koff]));
            ldsm_x4(af1, smem_u32(&A[(mb + 16 + a_row) * 72 + k0 + a_koff]));
            ldsm_x4(bf0, smem_u32(&Wh[(nb + b_n) * 72 + k0 + b_koff]));
            ldsm_x4(bf1, smem_u32(&Wh[(nb + 16 + b_n) * 72 + k0 + b_koff]));
            mma_f16(acc[0][0], af0, bf0[0], bf0[1]);
            mma_f16(acc[0][1], af0, bf0[2], bf0[3]);
            mma_f16(acc[0][2], af0, bf1[0], bf1[1]);
            mma_f16(acc[0][3], af0, bf1[2], bf1[3]);
            mma_f16(acc[1][0], af1, bf0[0], bf0[1]);
            mma_f16(acc[1][1], af1, bf0[2], bf0[3]);
            mma_f16(acc[1][2], af1, bf1[0], bf1[1]);
            mma_f16(acc[1][3], af1, bf1[2], bf1[3]);
        }

#pragma unroll
        for (int mi = 0; mi < 2; mi++) {
            int row = mb + mi * 16 + g;
            int dst0 = s_out[s][row];
            int dst1 = s_out[s][row + 8];
#pragma unroll
            for (int nj = 0; nj < 4; nj++) {
                int col = nb + nj * 8 + tg * 2;
                if (dst0 >= 0)
                    red_v2(g_x2 + (size_t)dst0 * 64 + col, acc[mi][nj][0], acc[mi][nj][1]);
                if (dst1 >= 0)
                    red_v2(g_x2 + (size_t)dst1 * 64 + col, acc[mi][nj][2], acc[mi][nj][3]);
            }
        }
    }
}

// ---------------- stats2 ------------------------------------------------------
__global__ void __launch_bounds__(256) stats2_kernel(const float* __restrict__ x,
                                                     const int* __restrict__ batch_idx,
                                                     float* __restrict__ gsum,
                                                     float* __restrict__ gsq) {
    __shared__ float sm[2048];
    int t = threadIdx.x;
    int r0 = blockIdx.x * 128;
    int r1 = min(r0 + 128, Nv);
    int cg = t & 15, rg = t >> 4;
    int b0 = batch_idx[r0], b1 = batch_idx[r1 - 1];

    if (b0 == b1) {
        float4 s = make_float4(0.f, 0.f, 0.f, 0.f);
        float4 q = make_float4(0.f, 0.f, 0.f, 0.f);
#pragma unroll 4
        for (int r = r0 + rg; r < r1; r += 16) {
            float4 v = *(const float4*)&x[(size_t)r * 64 + cg * 4];
            s.x += v.x; s.y += v.y; s.z += v.z; s.w += v.w;
            q.x += v.x * v.x; q.y += v.y * v.y; q.z += v.z * v.z; q.w += v.w * v.w;
        }
        *(float4*)&sm[rg * 64 + cg * 4]        = s;
        *(float4*)&sm[1024 + rg * 64 + cg * 4] = q;
        __syncthreads();
        if (t < 64) {
            float v = 0.f;
#pragma unroll
            for (int u = 0; u < 16; u++) v += sm[u * 64 + t];
            atomicAdd(&gsum[b0 * 64 + t], v);
        } else if (t < 128) {
            int c = t - 64;
            float v = 0.f;
#pragma unroll
            for (int u = 0; u < 16; u++) v += sm[1024 + u * 64 + c];
            atomicAdd(&gsq[b0 * 64 + c], v);
        }
    } else {
        for (int i = t; i < 512; i += 256) sm[i] = 0.f;
        __syncthreads();
        for (int r = r0 + rg; r < r1; r += 16) {
            int b = batch_idx[r];
            float4 v = *(const float4*)&x[(size_t)r * 64 + cg * 4];
            atomicAdd(&sm[b * 64 + cg * 4], v.x);
            atomicAdd(&sm[b * 64 + cg * 4 + 1], v.y);
            atomicAdd(&sm[b * 64 + cg * 4 + 2], v.z);
            atomicAdd(&sm[b * 64 + cg * 4 + 3], v.w);
            atomicAdd(&sm[256 + b * 64 + cg * 4], v.x * v.x);
            atomicAdd(&sm[256 + b * 64 + cg * 4 + 1], v.y * v.y);
            atomicAdd(&sm[256 + b * 64 + cg * 4 + 2], v.z * v.z);
            atomicAdd(&sm[256 + b * 64 + cg * 4 + 3], v.w * v.w);
        }
        __syncthreads();
        if (t < 256) {
            if (sm[t] != 0.f)       atomicAdd(&gsum[t], sm[t]);
            if (sm[256 + t] != 0.f) atomicAdd(&gsq[t], sm[256 + t]);
        }
    }
}

// ---------------- conv3: mma.sync fp16 single-A -> fp16 x3 + stats3 ----------
__global__ void __launch_bounds__(256, 2) conv3_mma_kernel(const int* __restrict__ batch_idx,
                                                           float* __restrict__ gsum,
                                                           float* __restrict__ gsq) {
    extern __shared__ __align__(16) char sm3[];
    __half* Ah = (__half*)sm3;
    __half* Wh = (__half*)(sm3 + 18432);
    float* Cs = (float*)sm3;
    __shared__ int s_b[128];
    __shared__ float sred[256], qred[256];

    int t = threadIdx.x;
    int row0 = blockIdx.x * 128;
    int col0 = blockIdx.y * 64;

    if (t < 128) {
        int r = row0 + t;
        s_b[t] = (r < Nv) ? batch_idx[r] : -1;
    }

#pragma unroll
    for (int e = t; e < 1024; e += 256) {
        int r = e >> 3, q = e & 7;
        int row = row0 + r;
        uint4 vh = make_uint4(0u, 0u, 0u, 0u);
        if (row < Nv) vh = *(const uint4*)&g_x2h[(size_t)row * 64 + q * 8];
        *(uint4*)&Ah[r * 72 + q * 8] = vh;
    }
#pragma unroll
    for (int e4 = t; e4 < 512; e4 += 256) {
        int n = e4 >> 3, q = e4 & 7;
        *(uint4*)&Wh[n * 72 + q * 8] = *(const uint4*)&g_W3h[(col0 + n) * 64 + q * 8];
    }
    __syncthreads();

    int wid = t >> 5, lane = t & 31;
    int mb = (wid >> 1) * 32;
    int nb = (wid & 1) * 32;

    float acc[2][4][4];
#pragma unroll
    for (int i = 0; i < 2; i++)
#pragma unroll
        for (int j = 0; j < 4; j++)
#pragma unroll
            for (int q = 0; q < 4; q++) acc[i][j][q] = 0.f;

    int a_row = lane & 15;
    int a_koff = (lane >> 4) << 3;
    int b_n = (lane & 7) + ((lane >> 4) << 3);
    int b_koff = ((lane >> 3) & 1) << 3;

#pragma unroll
    for (int ks = 0; ks < 4; ks++) {
        int k0 = ks * 16;
        uint32_t af0[4], af1[4], bf0[4], bf1[4];
        ldsm_x4(af0, smem_u32(&Ah[(mb + a_row) * 72 + k0 + a_koff]));
        ldsm_x4(af1, smem_u32(&Ah[(mb + 16 + a_row) * 72 + k0 + a_koff]));
        ldsm_x4(bf0, smem_u32(&Wh[(nb + b_n) * 72 + k0 + b_koff]));
        ldsm_x4(bf1, smem_u32(&Wh[(nb + 16 + b_n) * 72 + k0 + b_koff]));
        mma_f16(acc[0][0], af0, bf0[0], bf0[1]);
        mma_f16(acc[0][1], af0, bf0[2], bf0[3]);
        mma_f16(acc[0][2], af0, bf1[0], bf1[1]);
        mma_f16(acc[0][3], af0, bf1[2], bf1[3]);
        mma_f16(acc[1][0], af1, bf0[0], bf0[1]);
        mma_f16(acc[1][1], af1, bf0[2], bf0[3]);
        mma_f16(acc[1][2], af1, bf1[0], bf1[1]);
        mma_f16(acc[1][3], af1, bf1[2], bf1[3]);
    }

    __syncthreads();
    int g = lane >> 2, tg = lane & 3;
#pragma unroll
    for (int mi = 0; mi < 2; mi++) {
        int row = mb + mi * 16 + g;
#pragma unroll
        for (int nj = 0; nj < 4; nj++) {
            int col = nb + nj * 8 + tg * 2;
            *(float2*)&Cs[row * 68 + col]       = make_float2(acc[mi][nj][0], acc[mi][nj][1]);
            *(float2*)&Cs[(row + 8) * 68 + col] = make_float2(acc[mi][nj][2], acc[mi][nj][3]);
        }
    }
    __syncthreads();

    // write x3 slice as fp16 (8 ch per iteration)
#pragma unroll
    for (int e = t; e < 1024; e += 256) {
        int r = e >> 3, cg8 = e & 7;
        int row = row0 + r;
        if (row < Nv) {
            float4 v0 = *(const float4*)&Cs[r * 68 + cg8 * 8];
            float4 v1 = *(const float4*)&Cs[r * 68 + cg8 * 8 + 4];
            uint2 hi;
            uint2 lo = pack8h(v0.x, v0.y, v0.z, v0.w, v1.x, v1.y, v1.z, v1.w, hi);
            *(uint4*)&g_x3h[(size_t)row * 256 + col0 + cg8 * 8] =
                make_uint4(lo.x, lo.y, hi.x, hi.y);
        }
    }

    int b0 = s_b[0];
    bool fast;
    if (s_b[127] == b0) fast = true;
    else if (row0 + 127 >= Nv) {
        int lastr = Nv - 1 - row0;
        fast = (lastr >= 0 && s_b[lastr] == b0);
    } else fast = false;

    if (fast) {
        int col = t & 63, rg = t >> 6;
        float s = 0.f, q = 0.f;
#pragma unroll 8
        for (int r = rg * 32; r < rg * 32 + 32; r++) {
            float v = Cs[r * 68 + col];
            s += v; q += v * v;
        }
        sred[rg * 64 + col] = s;
        qred[rg * 64 + col] = q;
        __syncthreads();
        if (t < 64) {
            float v = sred[t] + sred[64 + t] + sred[128 + t] + sred[192 + t];
            atomicAdd(&gsum[b0 * 256 + col0 + t], v);
        } else if (t < 128) {
            int c = t - 64;
            float v = qred[c] + qred[64 + c] + qred[128 + c] + qred[192 + c];
            atomicAdd(&gsq[b0 * 256 + col0 + c], v);
        }
    } else {
        for (int e = t; e < 8192; e += 256) {
            int r = e >> 6, c = e & 63;
            if (row0 + r < Nv) {
                float v = Cs[r * 68 + c];
                int b = s_b[r];
                atomicAdd(&gsum[b * 256 + col0 + c], v);
                atomicAdd(&gsq[b * 256 + col0 + c], v * v);
            }
        }
    }
}

// ---------------- final: fused finalize3 + normalize + residual + relu -------
// 8-ch groups: uint4 x3h + 2x float4 feats -> 2x float4 out
__global__ void __launch_bounds__(256) final_kernel(float* __restrict__ y,
                                                    const float* __restrict__ feats,
                                                    const int* __restrict__ batch_idx,
                                                    const float* __restrict__ sumArr,
                                                    const float* __restrict__ sqArr) {
    __shared__ float s_m[Bb * 256], s_i[Bb * 256];
    int t = threadIdx.x;
    for (int i = t; i < Bb * 256; i += 256) {
        float cnt = (float)g_cnt[i >> 8];
        float mean = sumArr[i] / cnt;
        float var = sqArr[i] / cnt - mean * mean;
        s_m[i] = mean;
        s_i[i] = rsqrtf(fmaxf(var, 0.f) + EPSf);
    }
    __syncthreads();

    long long total = (long long)Nv * 32;   // 8-ch groups
    long long i = (long long)blockIdx.x * blockDim.x + t;
    long long stride = (long long)gridDim.x * blockDim.x;
    for (; i < total; i += stride) {
        int row = (int)(i >> 5);
        int cg8 = (int)(i & 31);
        int b = batch_idx[row];
        uint4 u = *(const uint4*)&g_x3h[(size_t)row * 256 + cg8 * 8];
        float4 f0 = ((const float4*)feats)[(size_t)row * 64 + cg8 * 2];
        float4 f1 = ((const float4*)feats)[(size_t)row * 64 + cg8 * 2 + 1];
        float4 m0 = ((const float4*)s_m)[b * 64 + cg8 * 2];
        float4 m1 = ((const float4*)s_m)[b * 64 + cg8 * 2 + 1];
        float4 s0 = ((const float4*)s_i)[b * 64 + cg8 * 2];
        float4 s1 = ((const float4*)s_i)[b * 64 + cg8 * 2 + 1];
        float2 x0 = __half22float2(*(__half2*)&u.x);
        float2 x1 = __half22float2(*(__half2*)&u.y);
        float2 x2 = __half22float2(*(__half2*)&u.z);
        float2 x3 = __half22float2(*(__half2*)&u.w);
        float4 o0, o1;
        o0.x = fmaxf((x0.x - m0.x) * s0.x + f0.x, 0.f);
        o0.y = fmaxf((x0.y - m0.y) * s0.y + f0.y, 0.f);
        o0.z = fmaxf((x1.x - m0.z) * s0.z + f0.z, 0.f);
        o0.w = fmaxf((x1.y - m0.w) * s0.w + f0.w, 0.f);
        o1.x = fmaxf((x2.x - m1.x) * s1.x + f1.x, 0.f);
        o1.y = fmaxf((x2.y - m1.y) * s1.y + f1.y, 0.f);
        o1.z = fmaxf((x3.x - m1.z) * s1.z + f1.z, 0.f);
        o1.w = fmaxf((x3.y - m1.w) * s1.w + f1.w, 0.f);
        ((float4*)y)[(size_t)row * 64 + cg8 * 2]     = o0;
        ((float4*)y)[(size_t)row * 64 + cg8 * 2 + 1] = o1;
    }
}

// ---------------- launch -----------------------------------------------------
extern "C" void kernel_launch(void* const* d_in, const int* in_sizes, int n_in,
                              void* d_out, int out_size) {
    const float* feats     = (const float*)d_in[0];
    const float* W1        = (const float*)d_in[1];
    const float* W2        = (const float*)d_in[2];
    const float* W3        = (const float*)d_in[3];
    const int*   in_idx    = (const int*)d_in[4];
    const int*   out_idx   = (const int*)d_in[5];
    const int*   batch_idx = (const int*)d_in[6];
    float* out = (float*)d_out;

    float *p_x2, *p_sum1, *p_sq1, *p_sum2, *p_sq2, *p_sum3, *p_sq3;
    __half *p_x1r, *p_x1h, *p_x2h;
    cudaGetSymbolAddress((void**)&p_x1r, g_x1r);
    cudaGetSymbolAddress((void**)&p_x2, g_x2);
    cudaGetSymbolAddress((void**)&p_x1h, g_x1h);
    cudaGetSymbolAddress((void**)&p_x2h, g_x2h);
    cudaGetSymbolAddress((void**)&p_sum1, g_sum1);
    cudaGetSymbolAddress((void**)&p_sq1, g_sq1);
    cudaGetSymbolAddress((void**)&p_sum2, g_sum2);
    cudaGetSymbolAddress((void**)&p_sq2, g_sq2);
    cudaGetSymbolAddress((void**)&p_sum3, g_sum3);
    cudaGetSymbolAddress((void**)&p_sq3, g_sq3);

    const int smem1 = 36864;
    const int smem2 = 46080;
    const int smem3 = 36864;
    cudaFuncSetAttribute(conv1_mma_kernel, cudaFuncAttributeMaxDynamicSharedMemorySize, smem1);
    cudaFuncSetAttribute(conv2_mma_kernel, cudaFuncAttributeMaxDynamicSharedMemorySize, smem2);
    cudaFuncSetAttribute(conv3_mma_kernel, cudaFuncAttributeMaxDynamicSharedMemorySize, smem3);

    small_zero_kernel<<<1, 256>>>();
    setup_kernel<<<2048, 256>>>(W1, W2, W3, batch_idx);

    // conv1 (tensor fp16) + fused stats1, fp16 raw x1
    conv1_mma_kernel<<<(Nv + 127) / 128, 256, smem1>>>(feats, batch_idx, p_sum1, p_sq1);

    // norm1 + relu -> fp16 (finalize fused, fp16 input)
    norm_h_kernel<<<8192, 256>>>(p_x1r, p_x1h, batch_idx, p_sum1, p_sq1);

    // conv2: persistent pipelined fp16 single-A, register-direct scatter
    conv2_mma_kernel<<<C2_GRID, 256, smem2>>>(in_idx, out_idx);
    stats2_kernel<<<(Nv + 127) / 128, 256>>>(p_x2, batch_idx, p_sum2, p_sq2);

    // norm2 + relu -> fp16 (finalize fused, fp32 input)
    norm_f_kernel<<<8192, 256>>>(p_x2, p_x2h, batch_idx, p_sum2, p_sq2);

    // conv3 (tensor fp16 single-A) -> fp16 x3 + fused stats3
    dim3 g3((Nv + 127) / 128, 4);
    conv3_mma_kernel<<<g3, 256, smem3>>>(batch_idx, p_sum3, p_sq3);

    // finalize3 fused + normalize + residual + relu
    final_kernel<<<8192, 256>>>(out, feats, batch_idx, p_sum3, p_sq3);
}